// round 1
// baseline (speedup 1.0000x reference)
#include <cuda_runtime.h>
#include <math.h>

namespace {

constexpr int B    = 4096;
constexpr int NHID = 512;
constexpr int BR   = 32;
constexpr int CAP  = 1024;   // smem list capacity (max group-stripe count << this)

// Scratch: per-sample log-prob contribution of levels 0 and 1.
__device__ float g_q0[B];
__device__ float g_q1[B];

// MODE 0: level 0 -> write g_q0
// MODE 1: level 1 -> write g_q1
// MODE 2: level 2 -> out[i] = expf(g_q0 + g_q1 + q2)
template <int MODE>
__global__ __launch_bounds__(128)
void hs_level_kernel(const float* __restrict__ inputs,
                     const int*   __restrict__ labels,
                     const float* __restrict__ W,
                     float*       __restrict__ out,
                     int node_div, int step_div, int level_offset, int nsub)
{
    __shared__ float xs[4][4][NHID];   // [warp][sample][h]  = 32 KB
    __shared__ int   list[CAP];
    __shared__ int   s_cnt;

    const int tid  = threadIdx.x;
    const int warp = tid >> 5;
    const int lane = tid & 31;
    const int cg   = lane & 7;    // column group: cols cg*4 .. cg*4+3
    const int hs   = lane >> 3;   // h stripe within 16-chunk

    const int g   = blockIdx.x / nsub;
    const int sub = blockIdx.x % nsub;

    if (tid == 0) s_cnt = 0;
    __syncthreads();

    // Compact this block's samples: stripe by (i % nsub), group by lab/node_div.
    for (int i = tid; i < B; i += blockDim.x) {
        if ((i % nsub) == sub) {
            int lab = labels[i];
            if (lab / node_div == g) {
                int p = atomicAdd(&s_cnt, 1);
                if (p < CAP) list[p] = i;
            }
        }
    }
    __syncthreads();
    const int cnt = min(s_cnt, CAP);

    const int node = level_offset + g;
    const float* __restrict__ Wn = W + (size_t)node * (NHID * BR);

    // Each warp takes batches of 4 samples.
    for (int base = warp * 4; base < cnt; base += 16) {
        const int rem = min(4, cnt - base);
        int idx[4], step[4];
        #pragma unroll
        for (int s = 0; s < 4; s++) {
            if (s < rem) {
                idx[s]  = list[base + s];
                step[s] = (labels[idx[s]] / step_div) % BR;
            } else {
                idx[s] = -1; step[s] = 0;
            }
        }

        // Stage x for the 4 samples into this warp's smem slab (zeros for pads).
        #pragma unroll
        for (int s = 0; s < 4; s++) {
            float4* dst = (float4*)xs[warp][s];
            if (idx[s] >= 0) {
                const float4* src = (const float4*)(inputs + (size_t)idx[s] * NHID);
                #pragma unroll
                for (int k = 0; k < 4; k++) dst[lane + 32 * k] = src[lane + 32 * k];
            } else {
                #pragma unroll
                for (int k = 0; k < 4; k++) dst[lane + 32 * k] = make_float4(0.f, 0.f, 0.f, 0.f);
            }
        }
        __syncwarp();

        // acc[s][j]: partial logit for column cg*4+j of sample s (over this lane's h-stripe)
        float acc[4][4];
        #pragma unroll
        for (int s = 0; s < 4; s++)
            #pragma unroll
            for (int j = 0; j < 4; j++) acc[s][j] = 0.f;

        const float* __restrict__ Wc = Wn + cg * 4;
        for (int hb = 0; hb < NHID; hb += 16) {
            const int h0 = hb + hs * 4;
            float4 xv[4];
            #pragma unroll
            for (int s = 0; s < 4; s++)
                xv[s] = *(const float4*)&xs[warp][s][h0];
            #pragma unroll
            for (int j = 0; j < 4; j++) {
                const float4 w4 = *(const float4*)&Wc[(size_t)(h0 + j) * BR];
                #pragma unroll
                for (int s = 0; s < 4; s++) {
                    const float xj = (&xv[s].x)[j];
                    acc[s][0] = fmaf(w4.x, xj, acc[s][0]);
                    acc[s][1] = fmaf(w4.y, xj, acc[s][1]);
                    acc[s][2] = fmaf(w4.z, xj, acc[s][2]);
                    acc[s][3] = fmaf(w4.w, xj, acc[s][3]);
                }
            }
        }
        __syncwarp();

        // Reduce over the 4 h-stripes (lanes cg, cg+8, cg+16, cg+24).
        #pragma unroll
        for (int off = 8; off <= 16; off <<= 1)
            #pragma unroll
            for (int s = 0; s < 4; s++)
                #pragma unroll
                for (int j = 0; j < 4; j++)
                    acc[s][j] += __shfl_xor_sync(0xffffffffu, acc[s][j], off);

        // Per-sample softmax across the 8 column-group lanes (width-8 butterflies).
        float q[4];
        #pragma unroll
        for (int s = 0; s < 4; s++) {
            float m = fmaxf(fmaxf(acc[s][0], acc[s][1]), fmaxf(acc[s][2], acc[s][3]));
            #pragma unroll
            for (int off = 1; off < 8; off <<= 1)
                m = fmaxf(m, __shfl_xor_sync(0xffffffffu, m, off));
            float e = expf(acc[s][0] - m) + expf(acc[s][1] - m)
                    + expf(acc[s][2] - m) + expf(acc[s][3] - m);
            #pragma unroll
            for (int off = 1; off < 8; off <<= 1)
                e += __shfl_xor_sync(0xffffffffu, e, off);
            const float lse = m + logf(e);
            float sel = (cg == (step[s] >> 2)) ? acc[s][step[s] & 3] : -INFINITY;
            #pragma unroll
            for (int off = 1; off < 8; off <<= 1)
                sel = fmaxf(sel, __shfl_xor_sync(0xffffffffu, sel, off));
            q[s] = sel - lse;
        }

        if (lane == 0) {
            #pragma unroll
            for (int s = 0; s < 4; s++) {
                if (idx[s] < 0) continue;
                if (MODE == 0)      g_q0[idx[s]] = q[s];
                else if (MODE == 1) g_q1[idx[s]] = q[s];
                else                out[idx[s]] = expf(g_q0[idx[s]] + g_q1[idx[s]] + q[s]);
            }
        }
        __syncwarp();   // protect xs before next batch overwrites it
    }
}

} // namespace

extern "C" void kernel_launch(void* const* d_in, const int* in_sizes, int n_in,
                              void* d_out, int out_size)
{
    const float* inputs = (const float*)d_in[0];
    const int*   labels = (const int*)d_in[1];
    const float* W      = (const float*)d_in[2];
    float*       out    = (float*)d_out;

    // Level 0: node 0, all samples.  1 group x 256 stripes -> 16 samples/block.
    hs_level_kernel<0><<<256, 128>>>(inputs, labels, W, out, 32768, 1024, 0, 256);
    // Level 1: nodes 1..32.  32 groups x 8 stripes -> ~16 samples/block.
    hs_level_kernel<1><<<256, 128>>>(inputs, labels, W, out, 1024, 32, 1, 8);
    // Level 2: nodes 33..1056.  1024 groups x 1 -> ~4 samples/block; combines + writes out.
    hs_level_kernel<2><<<1024, 128>>>(inputs, labels, W, out, 32, 1, 33, 1);
}

// round 2
// speedup vs baseline: 2.0307x; 2.0307x over previous
#include <cuda_runtime.h>
#include <math.h>

namespace {

constexpr int B      = 4096;
constexpr int NHID   = 512;
constexpr int BR     = 32;
constexpr int NG2    = 1024;   // level-2 groups
constexpr int WSLICE = NHID * BR;   // floats per node slice

// ---- persistent scratch (device globals; no allocation) ----
__device__ int   g_cnt[NG2];
__device__ int   g_run[NG2];
__device__ int   g_off[NG2 + 1];
__device__ int   g_perm[B];
__device__ int2  g_items[3584];    // {start | count<<16, node}
__device__ int   g_nitems;
__device__ float g_q0[B];
__device__ float g_q1[B];
__device__ float g_q2[B];

// ---------------- setup kernels ----------------

__global__ void hs_zero()
{
    int t = threadIdx.x;          // 1024 threads
    g_cnt[t] = 0;
    g_run[t] = 0;
}

__global__ void hs_hist(const int* __restrict__ labels)
{
    int i = blockIdx.x * blockDim.x + threadIdx.x;   // 16 x 256 = 4096
    int g = labels[i] >> 5;
    atomicAdd(&g_cnt[g], 1);
}

__device__ __forceinline__ int warp_incl_scan(int v)
{
    int lane = threadIdx.x & 31;
    #pragma unroll
    for (int o = 1; o < 32; o <<= 1) {
        int n = __shfl_up_sync(0xffffffffu, v, o);
        if (lane >= o) v += n;
    }
    return v;
}

// one block, 1024 threads: scan counts, build worklist
__global__ void hs_scan()
{
    __shared__ int sA[33];
    __shared__ int sB[33];
    __shared__ int s_base2;

    const int tid  = threadIdx.x;
    const int lane = tid & 31;
    const int w    = tid >> 5;

    const int c = g_cnt[tid];

    // scan 1: group offsets
    int inc = warp_incl_scan(c);
    if (lane == 31) sA[w] = inc;
    __syncthreads();
    if (w == 0) {
        int t  = sA[lane];
        int ti = warp_incl_scan(t);
        sA[lane] = ti - t;
        if (lane == 31) sA[32] = ti;
    }
    __syncthreads();
    const int off = inc - c + sA[w];
    g_off[tid] = off;
    if (tid == NG2 - 1) g_off[NG2] = off + c;

    // scan 2: level-2 item offsets (batch 4)
    const int nit2 = (c + 3) >> 2;
    int inc2 = warp_incl_scan(nit2);
    if (lane == 31) sB[w] = inc2;
    __syncthreads();
    if (w == 0) {
        int t  = sB[lane];
        int ti = warp_incl_scan(t);
        sB[lane] = ti - t;
        if (lane == 31) sB[32] = ti;
    }
    __syncthreads();
    const int ioff2 = inc2 - nit2 + sB[w];
    const int tot2  = sB[32];

    __syncthreads();   // g_off writes visible block-wide

    // level-1 items (batch 8), from 32 g1-group ranges
    int c1 = 0, it1off = 0;
    if (tid < 32) {
        c1 = g_off[(tid + 1) * 32] - g_off[tid * 32];
        int nit1 = (c1 + 7) >> 3;
        int i1 = warp_incl_scan(nit1);
        it1off = i1 - nit1;
        int tot1 = __shfl_sync(0xffffffffu, i1, 31);
        if (tid == 0) s_base2 = 512 + tot1;
    }
    __syncthreads();
    const int base2 = s_base2;

    // level-0 items: 512 items of 8 samples over sorted positions
    if (tid < 512)
        g_items[tid] = make_int2((tid * 8) | (8 << 16), 0);

    if (tid < 32) {
        int st = g_off[tid * 32];
        int n1 = (c1 + 7) >> 3;
        for (int k = 0; k < n1; k++) {
            int cc = min(8, c1 - 8 * k);
            g_items[512 + it1off + k] = make_int2((st + 8 * k) | (cc << 16), 1 + tid);
        }
    }

    // level-2 items
    for (int k = 0; k < nit2; k++) {
        int cc = min(4, c - 4 * k);
        g_items[base2 + ioff2 + k] = make_int2((off + 4 * k) | (cc << 16), 33 + tid);
    }

    if (tid == 0) g_nitems = base2 + tot2;
}

__global__ void hs_scatter(const int* __restrict__ labels)
{
    int i = blockIdx.x * blockDim.x + threadIdx.x;   // 16 x 256
    int lab = labels[i];
    int g = lab >> 5;
    int pos = g_off[g] + atomicAdd(&g_run[g], 1);
    g_perm[pos] = i;
}

// ---------------- main compute ----------------

template <int BATCH>
__device__ __forceinline__ void process_item(
    const float* __restrict__ inputs,
    const int*   __restrict__ labels,
    const float* __restrict__ W,
    int start, int count, int node, int lane)
{
    const int cg = lane & 7;      // column group (4 cols)
    const int hs = lane >> 3;     // h-stripe within 16-chunk

    int shift;
    float* qdst;
    if (node == 0)       { shift = 10; qdst = g_q0; }
    else if (node < 33)  { shift = 5;  qdst = g_q1; }
    else                 { shift = 0;  qdst = g_q2; }

    int idx[BATCH], step[BATCH];
    const float* xp[BATCH];
    #pragma unroll
    for (int s = 0; s < BATCH; s++) {
        int pos = start + ((s < count) ? s : (count - 1));
        int i = g_perm[pos];
        idx[s]  = i;
        step[s] = (labels[i] >> shift) & 31;
        xp[s]   = inputs + (size_t)i * NHID;
    }

    const float* __restrict__ Wn = W + (size_t)node * WSLICE + cg * 4;

    float acc[BATCH][4];
    #pragma unroll
    for (int s = 0; s < BATCH; s++)
        #pragma unroll
        for (int j = 0; j < 4; j++) acc[s][j] = 0.f;

    for (int hb = 0; hb < NHID; hb += 16) {
        const int h0 = hb + hs * 4;
        float4 w4[4];
        #pragma unroll
        for (int j = 0; j < 4; j++)
            w4[j] = *(const float4*)&Wn[(h0 + j) * BR];
        #pragma unroll
        for (int s = 0; s < BATCH; s++) {
            const float4 xv = *(const float4*)&xp[s][h0];
            #pragma unroll
            for (int j = 0; j < 4; j++) {
                const float xj = (&xv.x)[j];
                acc[s][0] = fmaf(w4[j].x, xj, acc[s][0]);
                acc[s][1] = fmaf(w4[j].y, xj, acc[s][1]);
                acc[s][2] = fmaf(w4[j].z, xj, acc[s][2]);
                acc[s][3] = fmaf(w4[j].w, xj, acc[s][3]);
            }
        }
    }

    // reduce over the 4 h-stripes (lanes cg, cg+8, cg+16, cg+24)
    #pragma unroll
    for (int off = 8; off <= 16; off <<= 1)
        #pragma unroll
        for (int s = 0; s < BATCH; s++)
            #pragma unroll
            for (int j = 0; j < 4; j++)
                acc[s][j] += __shfl_xor_sync(0xffffffffu, acc[s][j], off);

    // per-sample softmax across the 8 column-group lanes
    float q[BATCH];
    #pragma unroll
    for (int s = 0; s < BATCH; s++) {
        float m = fmaxf(fmaxf(acc[s][0], acc[s][1]), fmaxf(acc[s][2], acc[s][3]));
        #pragma unroll
        for (int o = 1; o < 8; o <<= 1)
            m = fmaxf(m, __shfl_xor_sync(0xffffffffu, m, o));
        float e = __expf(acc[s][0] - m) + __expf(acc[s][1] - m)
                + __expf(acc[s][2] - m) + __expf(acc[s][3] - m);
        #pragma unroll
        for (int o = 1; o < 8; o <<= 1)
            e += __shfl_xor_sync(0xffffffffu, e, o);
        const float lse = m + __logf(e);
        const int r = step[s] & 3;
        float v = (r == 0) ? acc[s][0] : (r == 1) ? acc[s][1]
                : (r == 2) ? acc[s][2] : acc[s][3];
        float sel = (cg == (step[s] >> 2)) ? v : -INFINITY;
        #pragma unroll
        for (int o = 1; o < 8; o <<= 1)
            sel = fmaxf(sel, __shfl_xor_sync(0xffffffffu, sel, o));
        q[s] = sel - lse;
    }

    if (lane == 0) {
        #pragma unroll
        for (int s = 0; s < BATCH; s++)
            if (s < count) qdst[idx[s]] = q[s];
    }
}

__global__ __launch_bounds__(256)
void hs_main(const float* __restrict__ inputs,
             const int*   __restrict__ labels,
             const float* __restrict__ W)
{
    const int lane = threadIdx.x & 31;
    const int gw   = (blockIdx.x << 3) + (threadIdx.x >> 5);
    const int nw   = gridDim.x << 3;
    const int nit  = g_nitems;

    for (int it = gw; it < nit; it += nw) {
        const int2 item  = g_items[it];
        const int  start = item.x & 0xffff;
        const int  count = item.x >> 16;
        const int  node  = item.y;
        if (count <= 4)
            process_item<4>(inputs, labels, W, start, count, node, lane);
        else
            process_item<8>(inputs, labels, W, start, count, node, lane);
    }
}

__global__ void hs_combine(float* __restrict__ out)
{
    int i = blockIdx.x * blockDim.x + threadIdx.x;   // 16 x 256
    out[i] = __expf(g_q0[i] + g_q1[i] + g_q2[i]);
}

} // namespace

extern "C" void kernel_launch(void* const* d_in, const int* in_sizes, int n_in,
                              void* d_out, int out_size)
{
    const float* inputs = (const float*)d_in[0];
    const int*   labels = (const int*)d_in[1];
    const float* W      = (const float*)d_in[2];
    float*       out    = (float*)d_out;

    hs_zero   <<<1, 1024>>>();
    hs_hist   <<<16, 256>>>(labels);
    hs_scan   <<<1, 1024>>>();
    hs_scatter<<<16, 256>>>(labels);
    hs_main   <<<296, 256>>>(inputs, labels, W);
    hs_combine<<<16, 256>>>(out);
}